// round 6
// baseline (speedup 1.0000x reference)
#include <cuda_runtime.h>
#include <cuda_fp16.h>
#include <cstdint>

typedef unsigned long long ull;

#define B_ 128
#define T_ 500
#define M_ 512
#define L_ 128
#define NROWS (B_ * T_)        // 64000

// ---- GEMM tiling ----
#define RM 64                  // rows per CTA
#define NC 256                 // interleaved (v,u) cols
#define KC 64                  // K per chunk
#define NCHUNK (M_ / KC)       // 8
#define ASTRIDE 144            // bytes per A row (128B data + 16 pad)
#define BSTRIDE 144

// per-stage smem layout (bytes)
#define A_HI 0
#define B_OFF (RM * ASTRIDE)             // 9216
#define STAGE (B_OFF + NC * BSTRIDE)     // 46080
#define DYN (2 * STAGE)                  // 92160

// ---- persistent device scratch ----
__device__ __half g_Bh[NC * M_];   // interleaved W^T fp16 [256][512]
__device__ float  g_C[NROWS * 2];  // C = H @ Wc  [64000][2]

// ============================ helpers ============================
__device__ __forceinline__ uint32_t smem_u32(const void* p) {
    uint32_t a;
    asm("{ .reg .u64 t; cvta.to.shared.u64 t, %1; cvt.u32.u64 %0, t; }" : "=r"(a) : "l"(p));
    return a;
}
__device__ __forceinline__ float sigm(float x) { return 1.0f / (1.0f + expf(-x)); }

__device__ __forceinline__ void ldsm_x4(uint32_t (&r)[4], uint32_t addr) {
    asm volatile("ldmatrix.sync.aligned.m8n8.x4.shared.b16 {%0,%1,%2,%3}, [%4];"
                 : "=r"(r[0]), "=r"(r[1]), "=r"(r[2]), "=r"(r[3]) : "r"(addr));
}
__device__ __forceinline__ void mma_f16(float (&c)[4], const uint32_t (&a)[4],
                                        uint32_t b0, uint32_t b1) {
    asm volatile(
        "mma.sync.aligned.m16n8k16.row.col.f32.f16.f16.f32 "
        "{%0,%1,%2,%3}, {%4,%5,%6,%7}, {%8,%9}, {%0,%1,%2,%3};"
        : "+f"(c[0]), "+f"(c[1]), "+f"(c[2]), "+f"(c[3])
        : "r"(a[0]), "r"(a[1]), "r"(a[2]), "r"(a[3]), "r"(b0), "r"(b1));
}
// packed fp32x2 -> fp16x2 convert (first src = HIGH half)
__device__ __forceinline__ uint32_t cvt_h2(float lo, float hi) {
    uint32_t r;
    asm("cvt.rn.f16x2.f32 %0, %1, %2;" : "=r"(r) : "f"(hi), "f"(lo));
    return r;
}
// packed f32x2 FMA: d += a * b
__device__ __forceinline__ ull pack2f(float lo, float hi) {
    ull r; asm("mov.b64 %0, {%1,%2};" : "=l"(r) : "f"(lo), "f"(hi)); return r;
}
__device__ __forceinline__ void fma2(ull& d, ull a, ull b) {
    asm("fma.rn.f32x2 %0, %1, %2, %0;" : "+l"(d) : "l"(a), "l"(b));
}
__device__ __forceinline__ float2 unpack2f(ull v) {
    float2 r; asm("mov.b64 {%0,%1}, %2;" : "=f"(r.x), "=f"(r.y) : "l"(v)); return r;
}
__device__ __forceinline__ void cpasync16(uint32_t dst, const void* src) {
    asm volatile("cp.async.cg.shared.global [%0], [%1], 16;" :: "r"(dst), "l"(src));
}
#define CP_COMMIT() asm volatile("cp.async.commit_group;" ::: "memory")
#define CP_WAIT0()  asm volatile("cp.async.wait_group 0;" ::: "memory")

// ============================================================================
// prep: interleaved W^T to fp16.  col 2j -> Wv[:,j], col 2j+1 -> Wu[:,j]
// ============================================================================
__global__ void prep_kernel(const float* __restrict__ Wv, const float* __restrict__ Wu) {
    int n = blockIdx.x;        // 0..255
    int k = threadIdx.x;       // 0..511
    int j = n >> 1;
    float x = (n & 1) ? Wu[k * L_ + j] : Wv[k * L_ + j];
    g_Bh[n * M_ + k] = __float2half_rn(x);
}

// ============================================================================
// GEMM (fp16 x fp16 via mma.sync) + fused gate/Wa epilogue + fp32 C=H@Wc
// grid = 1000, block = 256 (8 warps: 2 M x 4 N), CTA tile 64 x 256, K = 512
// ============================================================================
__global__ void __launch_bounds__(256, 2) gemm_attn_kernel(
    const float* __restrict__ H,  const float* __restrict__ bv,
    const float* __restrict__ bu, const float* __restrict__ Wa,
    const float* __restrict__ ba, const float* __restrict__ Wc,
    float* __restrict__ A_raw)
{
    extern __shared__ char sm[];
    __shared__ float bvS[L_], buS[L_], WaS[L_];
    __shared__ float2 WcPS[M_];          // (Wc[k][0], Wc[k][1]) pairs
    __shared__ float red[RM][4];

    const int tid  = threadIdx.x;
    const int lane = tid & 31;
    const int warp = tid >> 5;
    const int wm   = warp >> 2;      // 0..1
    const int wn   = warp & 3;       // 0..3
    const size_t n0 = (size_t)blockIdx.x * RM;

    if (tid < L_) { bvS[tid] = bv[tid]; buS[tid] = bu[tid]; WaS[tid] = Wa[tid]; }
#pragma unroll
    for (int i = 0; i < 2; i++) {
        int k = i * 256 + tid;
        WcPS[k] = ((const float2*)Wc)[k];     // contiguous (w0,w1) pairs
    }

    float acc[2][8][4];
#pragma unroll
    for (int mt = 0; mt < 2; mt++)
#pragma unroll
        for (int nt = 0; nt < 8; nt++)
#pragma unroll
            for (int i = 0; i < 4; i++) acc[mt][nt][i] = 0.0f;

    float4 ar[4];                    // A staging regs (fp32, also feeds C)
    ull ccp[4];                      // packed (c0,c1) accumulators, 4 rows
#pragma unroll
    for (int i = 0; i < 4; i++) ccp[i] = 0ULL;

    const uint32_t smb = smem_u32(sm);

    // LDSM per-thread offsets (within a stage)
    const uint32_t a_ld_row  = (uint32_t)(wm * 32 + (lane & 15));
    const uint32_t a_ld_koff = (uint32_t)((lane >> 4) * 16);
    const uint32_t b_ld_n    = (uint32_t)(wn * 64 + (lane & 7) + ((lane >> 4) << 3));
    const uint32_t b_ld_koff = (uint32_t)(((lane >> 3) & 1) * 16);

    // C-accum mapping: thread covers rows (tid>>4)+16i, k-slice c_f4*4..+3
    const int c_f4 = tid & 15;

#define LOADG_A(c)                                                                 \
    {                                                                              \
        const int kt = (c) * KC;                                                   \
        _Pragma("unroll")                                                          \
        for (int i = 0; i < 4; i++) {                                              \
            int idx = i * 256 + tid;                                               \
            int row = idx >> 4, f4 = idx & 15;                                     \
            ar[i] = *(const float4*)(H + (n0 + row) * M_ + kt + f4 * 4);           \
        }                                                                          \
    }

#define C_ACCUM(c)                                                                 \
    {                                                                              \
        const int kb = (c) * KC + c_f4 * 4;                                        \
        ull w0 = *(const ull*)&WcPS[kb + 0];                                       \
        ull w1 = *(const ull*)&WcPS[kb + 1];                                       \
        ull w2 = *(const ull*)&WcPS[kb + 2];                                       \
        ull w3 = *(const ull*)&WcPS[kb + 3];                                       \
        _Pragma("unroll")                                                          \
        for (int i = 0; i < 4; i++) {                                              \
            fma2(ccp[i], pack2f(ar[i].x, ar[i].x), w0);                            \
            fma2(ccp[i], pack2f(ar[i].y, ar[i].y), w1);                            \
            fma2(ccp[i], pack2f(ar[i].z, ar[i].z), w2);                            \
            fma2(ccp[i], pack2f(ar[i].w, ar[i].w), w3);                            \
        }                                                                          \
    }

#define CPASYNC_B(c, buf)                                                          \
    {                                                                              \
        const int kt = (c) * KC;                                                   \
        const uint32_t db = smb + (buf) * STAGE + B_OFF;                           \
        _Pragma("unroll")                                                          \
        for (int i = 0; i < 8; i++) {                                              \
            int idx = i * 256 + tid;                                               \
            int n = idx >> 3, k16 = idx & 7;                                       \
            cpasync16(db + n * BSTRIDE + k16 * 16, g_Bh + n * M_ + kt + k16 * 8);  \
        }                                                                          \
        CP_COMMIT();                                                               \
    }

#define STORE_A(buf)                                                               \
    {                                                                              \
        char* sb = sm + (buf) * STAGE;                                             \
        _Pragma("unroll")                                                          \
        for (int i = 0; i < 4; i++) {                                              \
            int idx = i * 256 + tid;                                               \
            int row = idx >> 4, f4 = idx & 15;                                     \
            float4 x = ar[i];                                                      \
            uint32_t off = (uint32_t)(row * ASTRIDE + f4 * 8);                     \
            *(uint2*)(sb + A_HI + off) =                                           \
                make_uint2(cvt_h2(x.x, x.y), cvt_h2(x.z, x.w));                    \
        }                                                                          \
    }

#define COMPUTE(buf)                                                               \
    {                                                                              \
        const uint32_t sbase = smb + (buf) * STAGE;                                \
        _Pragma("unroll")                                                          \
        for (int ks = 0; ks < 4; ks++) {                                           \
            uint32_t ah[2][4];                                                     \
            _Pragma("unroll")                                                      \
            for (int mt = 0; mt < 2; mt++) {                                       \
                uint32_t aoff = (a_ld_row + mt * 16) * ASTRIDE + ks * 32 + a_ld_koff; \
                ldsm_x4(ah[mt], sbase + A_HI + aoff);                              \
            }                                                                      \
            _Pragma("unroll")                                                      \
            for (int p = 0; p < 4; p++) {                                          \
                uint32_t br[4];                                                    \
                uint32_t boff = (b_ld_n + p * 16) * BSTRIDE + ks * 32 + b_ld_koff; \
                ldsm_x4(br, sbase + B_OFF + boff);                                 \
                _Pragma("unroll")                                                  \
                for (int mt = 0; mt < 2; mt++) {                                   \
                    mma_f16(acc[mt][2 * p],     ah[mt], br[0], br[1]);             \
                    mma_f16(acc[mt][2 * p + 1], ah[mt], br[2], br[3]);             \
                }                                                                  \
            }                                                                      \
        }                                                                          \
    }

    // ---- pipelined main loop ----
    CPASYNC_B(0, 0);
    LOADG_A(0);
    __syncthreads();            // WcPS ready for C_ACCUM
    C_ACCUM(0);
    STORE_A(0);
    CP_WAIT0();
    __syncthreads();
#pragma unroll 1
    for (int c = 0; c < NCHUNK; c++) {
        const int buf = c & 1;
        if (c + 1 < NCHUNK) {
            CPASYNC_B(c + 1, buf ^ 1);
            LOADG_A(c + 1);
            C_ACCUM(c + 1);
        }
        COMPUTE(buf);
        if (c + 1 < NCHUNK) {
            STORE_A(buf ^ 1);
            CP_WAIT0();
        }
        __syncthreads();
    }

    // ---- C reduce over the 16-lane k-slice groups, write fp32 C ----
#pragma unroll
    for (int i = 0; i < 4; i++) {
        float2 cv = unpack2f(ccp[i]);
#pragma unroll
        for (int o = 1; o < 16; o <<= 1) {
            cv.x += __shfl_xor_sync(~0u, cv.x, o);
            cv.y += __shfl_xor_sync(~0u, cv.y, o);
        }
        if (c_f4 == 0) {
            int r0 = tid >> 4;     // 0..15
            *(float2*)(g_C + (n0 + r0 + 16 * i) * 2) = cv;
        }
    }

    // ---- fused epilogue: gate + Wa dot, in-thread (v,u) pairs ----
#pragma unroll
    for (int mt = 0; mt < 2; mt++) {
        float p0 = 0.0f, p1 = 0.0f;
#pragma unroll
        for (int nt = 0; nt < 8; nt++) {
            int j = wn * 32 + nt * 4 + (lane & 3);
            float bvj = bvS[j], buj = buS[j], waj = WaS[j];
            p0 += tanhf(acc[mt][nt][0] + bvj) * sigm(acc[mt][nt][1] + buj) * waj;
            p1 += tanhf(acc[mt][nt][2] + bvj) * sigm(acc[mt][nt][3] + buj) * waj;
        }
        p0 += __shfl_xor_sync(~0u, p0, 1); p0 += __shfl_xor_sync(~0u, p0, 2);
        p1 += __shfl_xor_sync(~0u, p1, 1); p1 += __shfl_xor_sync(~0u, p1, 2);
        if ((lane & 3) == 0) {
            int r = wm * 32 + mt * 16 + (lane >> 2);
            red[r][wn] = p0;
            red[r + 8][wn] = p1;
        }
    }
    __syncthreads();
    if (tid < RM) {
        float s = red[tid][0] + red[tid][1] + red[tid][2] + red[tid][3] + __ldg(ba);
        A_raw[n0 + tid] = s;
    }
}

// ============================================================================
// pool: per bag — softmax over T, then out[b] = sum_t w[t] * C[t]  (+bc)
// grid = 128, block = 512
// ============================================================================
__global__ void __launch_bounds__(512) pool_kernel(
    const float* __restrict__ A_raw, const float* __restrict__ bc,
    float* __restrict__ A_sm, float* __restrict__ out)
{
    __shared__ float red[16], redB[16];
    __shared__ float sh_mx, sh_sum;

    const int tid = threadIdx.x;
    const int b = blockIdx.x;
    const int lane = tid & 31, wid = tid >> 5;

    float a = (tid < T_) ? A_raw[b * T_ + tid] : -1e30f;
    float m = a;
#pragma unroll
    for (int o = 16; o; o >>= 1) m = fmaxf(m, __shfl_xor_sync(~0u, m, o));
    if (lane == 0) red[wid] = m;
    __syncthreads();
    if (tid < 32) {
        float v = (tid < 16) ? red[tid] : -1e30f;
#pragma unroll
        for (int o = 16; o; o >>= 1) v = fmaxf(v, __shfl_xor_sync(~0u, v, o));
        if (tid == 0) sh_mx = v;
    }
    __syncthreads();
    float e = (tid < T_) ? expf(a - sh_mx) : 0.0f;
    float s = e;
#pragma unroll
    for (int o = 16; o; o >>= 1) s += __shfl_xor_sync(~0u, s, o);
    __syncthreads();
    if (lane == 0) red[wid] = s;
    __syncthreads();
    if (tid < 32) {
        float v = (tid < 16) ? red[tid] : 0.0f;
#pragma unroll
        for (int o = 16; o; o >>= 1) v += __shfl_xor_sync(~0u, v, o);
        if (tid == 0) sh_sum = v;
    }
    __syncthreads();

    float wt = 0.0f;
    if (tid < T_) {
        wt = e / sh_sum;
        A_sm[b * T_ + tid] = wt;
    }

    float c0 = 0.0f, c1 = 0.0f;
    if (tid < T_) {
        float2 cv = *(const float2*)(g_C + (b * T_ + tid) * 2);
        c0 = wt * cv.x;
        c1 = wt * cv.y;
    }
#pragma unroll
    for (int o = 16; o; o >>= 1) {
        c0 += __shfl_xor_sync(~0u, c0, o);
        c1 += __shfl_xor_sync(~0u, c1, o);
    }
    __syncthreads();
    if (lane == 0) { red[wid] = c0; redB[wid] = c1; }
    __syncthreads();
    if (tid == 0) {
        float r0 = 0.0f, r1 = 0.0f;
#pragma unroll
        for (int i = 0; i < 16; i++) { r0 += red[i]; r1 += redB[i]; }
        out[b * 2 + 0] = r0 + bc[0];
        out[b * 2 + 1] = r1 + bc[1];
    }
}

// ============================================================================
// Launch. Output layout: [out (B*2) | A_sm (B*T) | A_t raw logits (B*T)]
// ============================================================================
extern "C" void kernel_launch(void* const* d_in, const int* in_sizes, int n_in,
                              void* d_out, int out_size)
{
    const float* H  = (const float*)d_in[0];
    const float* Wv = (const float*)d_in[1];
    const float* bv = (const float*)d_in[2];
    const float* Wu = (const float*)d_in[3];
    const float* bu = (const float*)d_in[4];
    const float* Wa = (const float*)d_in[5];
    const float* ba = (const float*)d_in[6];
    const float* Wc = (const float*)d_in[7];
    const float* bc = (const float*)d_in[8];

    float* out   = (float*)d_out;
    float* A_sm  = out + B_ * 2;
    float* A_raw = A_sm + B_ * T_;

    cudaFuncSetAttribute(gemm_attn_kernel,
                         cudaFuncAttributeMaxDynamicSharedMemorySize, DYN);

    prep_kernel<<<NC, M_>>>(Wv, Wu);
    gemm_attn_kernel<<<NROWS / RM, 256, DYN>>>(H, bv, bu, Wa, ba, Wc, A_raw);
    pool_kernel<<<B_, 512>>>(A_raw, bc, A_sm, out);
}